// round 5
// baseline (speedup 1.0000x reference)
#include <cuda_runtime.h>

#define BB 4
#define NN 50000
#define DD 256
#define EE 800000
#define TAU_MIN 0.001f
#define MAX_CORR 0.15f

// Ping-pong position buffers, padded to float4 per node for vector atomics.
__device__ float4 g_x0[BB * NN];
__device__ float4 g_x1[BB * NN];

// ---------------------------------------------------------------------------
// Kernel 1: x_pred = keypoints + tau * (hand_tokens @ head_w + head_b)
// One warp per (b, n) row. Lane-strided k => coalesced 128B global loads and
// conflict-free shared-memory reads of W.
// ---------------------------------------------------------------------------
__global__ __launch_bounds__(256) void pred_kernel(
    const float* __restrict__ kp,     // [B,N,3]
    const float* __restrict__ ts,     // [B]
    const float* __restrict__ ht,     // [B,N,D]
    const float* __restrict__ hw,     // [D,3]
    const float* __restrict__ hb,     // [3]
    float4* __restrict__ x)           // [B*N]
{
    __shared__ float sw0[DD], sw1[DD], sw2[DD];
    int tid = threadIdx.x;
    for (int k = tid; k < DD; k += blockDim.x) {
        sw0[k] = hw[k * 3 + 0];
        sw1[k] = hw[k * 3 + 1];
        sw2[k] = hw[k * 3 + 2];
    }
    __syncthreads();

    int warp = (blockIdx.x * blockDim.x + tid) >> 5;
    int lane = tid & 31;
    if (warp >= BB * NN) return;

    const float* row = ht + (size_t)warp * DD;
    float a0 = 0.f, a1 = 0.f, a2 = 0.f;
#pragma unroll
    for (int i = 0; i < DD / 32; ++i) {
        int k = lane + 32 * i;
        float v = row[k];
        a0 = fmaf(v, sw0[k], a0);
        a1 = fmaf(v, sw1[k], a1);
        a2 = fmaf(v, sw2[k], a2);
    }
#pragma unroll
    for (int off = 16; off > 0; off >>= 1) {
        a0 += __shfl_down_sync(0xffffffffu, a0, off);
        a1 += __shfl_down_sync(0xffffffffu, a1, off);
        a2 += __shfl_down_sync(0xffffffffu, a2, off);
    }
    if (lane == 0) {
        int b = warp / NN;
        float tau = fmaxf(1.0f - ts[b], TAU_MIN);
        float4 r;
        r.x = kp[3 * warp + 0] + tau * (a0 + hb[0]);
        r.y = kp[3 * warp + 1] + tau * (a1 + hb[1]);
        r.z = kp[3 * warp + 2] + tau * (a2 + hb[2]);
        r.w = 0.0f;
        x[warp] = r;
    }
}

// ---------------------------------------------------------------------------
// Kernel 2: one XPBD Jacobi iteration. xn was pre-initialized to a copy of
// xc; corrections accumulate into xn via red.global.add.v4.f32 (sm_90+).
// One thread handles one edge for ALL batches (edge data read once, 8
// independent L2-resident gathers => high MLP).
// ---------------------------------------------------------------------------
__global__ __launch_bounds__(256) void edge_kernel(
    const float4* __restrict__ xc,
    float4* __restrict__ xn,
    const int* __restrict__ ei,      // [2,E]
    const float* __restrict__ rl)    // [E]
{
    int e = blockIdx.x * blockDim.x + threadIdx.x;
    if (e >= EE) return;
    int s = ei[e];
    int d = ei[EE + e];
    float L0 = rl[e];
    const float denom = 2.0f;  // w_i + w_j + alpha(=0) + 1e-9 rounds to 2 in fp32

#pragma unroll
    for (int b = 0; b < BB; ++b) {
        const float4* xb = xc + b * NN;
        float4 xs = __ldg(&xb[s]);
        float4 xd = __ldg(&xb[d]);
        float dx = xs.x - xd.x;
        float dy = xs.y - xd.y;
        float dz = xs.z - xd.z;
        float dist = sqrtf(dx * dx + dy * dy + dz * dz);
        // correction = clip( (-(dist-L0)/denom) * diff/(dist+1e-9), +-0.15 )
        float scale = -(dist - L0) / (denom * (dist + 1e-9f));
        float cx = fminf(fmaxf(scale * dx, -MAX_CORR), MAX_CORR);
        float cy = fminf(fmaxf(scale * dy, -MAX_CORR), MAX_CORR);
        float cz = fminf(fmaxf(scale * dz, -MAX_CORR), MAX_CORR);

        float4* xnb = xn + b * NN;
        asm volatile("red.global.add.v4.f32 [%0], {%1,%2,%3,%4};"
                     :: "l"(xnb + s), "f"(cx), "f"(cy), "f"(cz), "f"(0.0f)
                     : "memory");
        asm volatile("red.global.add.v4.f32 [%0], {%1,%2,%3,%4};"
                     :: "l"(xnb + d), "f"(-cx), "f"(-cy), "f"(-cz), "f"(0.0f)
                     : "memory");
    }
}

// ---------------------------------------------------------------------------
// Kernel 3: v_eff = (x_corrected - keypoints) / tau
// ---------------------------------------------------------------------------
__global__ __launch_bounds__(256) void out_kernel(
    const float4* __restrict__ x,
    const float* __restrict__ kp,
    const float* __restrict__ ts,
    float* __restrict__ out)
{
    int i = blockIdx.x * blockDim.x + threadIdx.x;
    if (i >= BB * NN) return;
    int b = i / NN;
    float tau = fmaxf(1.0f - ts[b], TAU_MIN);
    float4 v = x[i];
    out[3 * i + 0] = (v.x - kp[3 * i + 0]) / tau;
    out[3 * i + 1] = (v.y - kp[3 * i + 1]) / tau;
    out[3 * i + 2] = (v.z - kp[3 * i + 2]) / tau;
}

extern "C" void kernel_launch(void* const* d_in, const int* in_sizes, int n_in,
                              void* d_out, int out_size)
{
    const float* kp = (const float*)d_in[0];   // keypoints   [B,N,3]
    const float* ts = (const float*)d_in[1];   // timesteps   [B]
    const float* ht = (const float*)d_in[2];   // hand_tokens [B,N,D]
    const float* hw = (const float*)d_in[3];   // head_w      [D,3]
    const float* hb = (const float*)d_in[4];   // head_b      [3]
    const int*   ei = (const int*)d_in[5];     // edge_index  [2,E]
    const float* rl = (const float*)d_in[6];   // rest_lengths[E]
    float* out = (float*)d_out;

    float4 *x0, *x1;
    cudaGetSymbolAddress((void**)&x0, g_x0);
    cudaGetSymbolAddress((void**)&x1, g_x1);

    // Prediction head: one warp per row, 8 warps/block.
    {
        int warps = BB * NN;
        int threads = 256;
        int blocks = (warps * 32 + threads - 1) / threads;
        pred_kernel<<<blocks, threads>>>(kp, ts, ht, hw, hb, x0);
    }

    // 4 Jacobi XPBD iterations with ping-pong buffers.
    float4* cur = x0;
    float4* nxt = x1;
    for (int it = 0; it < 4; ++it) {
        cudaMemcpyAsync(nxt, cur, sizeof(float4) * BB * NN,
                        cudaMemcpyDeviceToDevice);
        int threads = 256;
        int blocks = (EE + threads - 1) / threads;
        edge_kernel<<<blocks, threads>>>(cur, nxt, ei, rl);
        float4* t = cur; cur = nxt; nxt = t;
    }

    // Final velocity.
    {
        int threads = 256;
        int blocks = (BB * NN + threads - 1) / threads;
        out_kernel<<<blocks, threads>>>(cur, kp, ts, out);
    }
}

// round 6
// speedup vs baseline: 1.0570x; 1.0570x over previous
#include <cuda_runtime.h>

#define BB 4
#define NN 50000
#define DD 256
#define EE 800000
#define TAU_MIN 0.001f
#define MAX_CORR 0.15f

// Ping-pong position buffers. Layout: x[node][batch] (batch-interleaved),
// so one node's 4 batch slots are 64B contiguous & 64B-aligned -> the 4
// per-batch gathers / vector-reds of an edge endpoint fill whole 32B
// sectors instead of wasting half of each.
__device__ float4 g_x0[NN * BB];
__device__ float4 g_x1[NN * BB];

// ---------------------------------------------------------------------------
// Kernel 1: x_pred = keypoints + tau * (hand_tokens @ head_w + head_b)
// One warp per (b, n) row; writes to interleaved layout x[n*BB + b].
// ---------------------------------------------------------------------------
__global__ __launch_bounds__(256) void pred_kernel(
    const float* __restrict__ kp,     // [B,N,3]
    const float* __restrict__ ts,     // [B]
    const float* __restrict__ ht,     // [B,N,D]
    const float* __restrict__ hw,     // [D,3]
    const float* __restrict__ hb,     // [3]
    float4* __restrict__ x)           // [N*B] interleaved
{
    __shared__ float sw0[DD], sw1[DD], sw2[DD];
    int tid = threadIdx.x;
    for (int k = tid; k < DD; k += blockDim.x) {
        sw0[k] = hw[k * 3 + 0];
        sw1[k] = hw[k * 3 + 1];
        sw2[k] = hw[k * 3 + 2];
    }
    __syncthreads();

    int warp = (blockIdx.x * blockDim.x + tid) >> 5;
    int lane = tid & 31;
    if (warp >= BB * NN) return;

    const float* row = ht + (size_t)warp * DD;
    float a0 = 0.f, a1 = 0.f, a2 = 0.f;
#pragma unroll
    for (int i = 0; i < DD / 32; ++i) {
        int k = lane + 32 * i;
        float v = row[k];
        a0 = fmaf(v, sw0[k], a0);
        a1 = fmaf(v, sw1[k], a1);
        a2 = fmaf(v, sw2[k], a2);
    }
#pragma unroll
    for (int off = 16; off > 0; off >>= 1) {
        a0 += __shfl_down_sync(0xffffffffu, a0, off);
        a1 += __shfl_down_sync(0xffffffffu, a1, off);
        a2 += __shfl_down_sync(0xffffffffu, a2, off);
    }
    if (lane == 0) {
        int b = warp / NN;
        int n = warp - b * NN;
        float tau = fmaxf(1.0f - ts[b], TAU_MIN);
        float4 r;
        r.x = kp[3 * warp + 0] + tau * (a0 + hb[0]);
        r.y = kp[3 * warp + 1] + tau * (a1 + hb[1]);
        r.z = kp[3 * warp + 2] + tau * (a2 + hb[2]);
        r.w = 0.0f;
        x[n * BB + b] = r;
    }
}

// ---------------------------------------------------------------------------
// Kernel 2: one XPBD Jacobi iteration. xn pre-initialized to copy of xc;
// corrections accumulate via red.global.add.v4.f32. One thread = one edge,
// all 4 batches; interleaved layout makes the 4 gathers of each endpoint
// (and the 4 reds) a contiguous 64B burst = 2 fully-used sectors.
// ---------------------------------------------------------------------------
__global__ __launch_bounds__(256) void edge_kernel(
    const float4* __restrict__ xc,
    float4* __restrict__ xn,
    const int* __restrict__ ei,      // [2,E]
    const float* __restrict__ rl)    // [E]
{
    int e = blockIdx.x * blockDim.x + threadIdx.x;
    if (e >= EE) return;
    int s = ei[e];
    int d = ei[EE + e];
    float L0 = rl[e];
    const float denom = 2.0f;  // w_i + w_j + alpha(=0) + 1e-9 == 2.0f in fp32

    const float4* xsp = xc + (size_t)s * BB;
    const float4* xdp = xc + (size_t)d * BB;

    // Issue all 8 gathers up front for max MLP.
    float4 xs[BB], xd[BB];
#pragma unroll
    for (int b = 0; b < BB; ++b) xs[b] = __ldg(&xsp[b]);
#pragma unroll
    for (int b = 0; b < BB; ++b) xd[b] = __ldg(&xdp[b]);

    float4* xns = xn + (size_t)s * BB;
    float4* xnd = xn + (size_t)d * BB;

#pragma unroll
    for (int b = 0; b < BB; ++b) {
        float dx = xs[b].x - xd[b].x;
        float dy = xs[b].y - xd[b].y;
        float dz = xs[b].z - xd[b].z;
        float dist = sqrtf(dx * dx + dy * dy + dz * dz);
        float scale = -(dist - L0) / (denom * (dist + 1e-9f));
        float cx = fminf(fmaxf(scale * dx, -MAX_CORR), MAX_CORR);
        float cy = fminf(fmaxf(scale * dy, -MAX_CORR), MAX_CORR);
        float cz = fminf(fmaxf(scale * dz, -MAX_CORR), MAX_CORR);

        asm volatile("red.global.add.v4.f32 [%0], {%1,%2,%3,%4};"
                     :: "l"(xns + b), "f"(cx), "f"(cy), "f"(cz), "f"(0.0f)
                     : "memory");
        asm volatile("red.global.add.v4.f32 [%0], {%1,%2,%3,%4};"
                     :: "l"(xnd + b), "f"(-cx), "f"(-cy), "f"(-cz), "f"(0.0f)
                     : "memory");
    }
}

// ---------------------------------------------------------------------------
// Kernel 3: v_eff = (x_corrected - keypoints) / tau
// ---------------------------------------------------------------------------
__global__ __launch_bounds__(256) void out_kernel(
    const float4* __restrict__ x,     // interleaved [N*B]
    const float* __restrict__ kp,
    const float* __restrict__ ts,
    float* __restrict__ out)
{
    int i = blockIdx.x * blockDim.x + threadIdx.x;   // b*NN + n
    if (i >= BB * NN) return;
    int b = i / NN;
    int n = i - b * NN;
    float tau = fmaxf(1.0f - ts[b], TAU_MIN);
    float4 v = x[n * BB + b];
    out[3 * i + 0] = (v.x - kp[3 * i + 0]) / tau;
    out[3 * i + 1] = (v.y - kp[3 * i + 1]) / tau;
    out[3 * i + 2] = (v.z - kp[3 * i + 2]) / tau;
}

extern "C" void kernel_launch(void* const* d_in, const int* in_sizes, int n_in,
                              void* d_out, int out_size)
{
    const float* kp = (const float*)d_in[0];   // keypoints   [B,N,3]
    const float* ts = (const float*)d_in[1];   // timesteps   [B]
    const float* ht = (const float*)d_in[2];   // hand_tokens [B,N,D]
    const float* hw = (const float*)d_in[3];   // head_w      [D,3]
    const float* hb = (const float*)d_in[4];   // head_b      [3]
    const int*   ei = (const int*)d_in[5];     // edge_index  [2,E]
    const float* rl = (const float*)d_in[6];   // rest_lengths[E]
    float* out = (float*)d_out;

    float4 *x0, *x1;
    cudaGetSymbolAddress((void**)&x0, g_x0);
    cudaGetSymbolAddress((void**)&x1, g_x1);

    // Prediction head: one warp per row, 8 warps/block.
    {
        int warps = BB * NN;
        int threads = 256;
        int blocks = (warps * 32 + threads - 1) / threads;
        pred_kernel<<<blocks, threads>>>(kp, ts, ht, hw, hb, x0);
    }

    // 4 Jacobi XPBD iterations with ping-pong buffers.
    float4* cur = x0;
    float4* nxt = x1;
    for (int it = 0; it < 4; ++it) {
        cudaMemcpyAsync(nxt, cur, sizeof(float4) * BB * NN,
                        cudaMemcpyDeviceToDevice);
        int threads = 256;
        int blocks = (EE + threads - 1) / threads;
        edge_kernel<<<blocks, threads>>>(cur, nxt, ei, rl);
        float4* t = cur; cur = nxt; nxt = t;
    }

    // Final velocity.
    {
        int threads = 256;
        int blocks = (BB * NN + threads - 1) / threads;
        out_kernel<<<blocks, threads>>>(cur, kp, ts, out);
    }
}